// round 7
// baseline (speedup 1.0000x reference)
#include <cuda_runtime.h>
#include <cstdint>

#define NS 65536
#define D  32
#define R  128
#define S  16         // samples per group (one group = 2 warps, half rules each)
#define GPB 4         // groups per block -> 8 warps, 256 threads, 64 samples/block

typedef unsigned long long ull;

// smem layout (bytes):
//   sWV [D][64 pairs][w0,w1,v0,v1] @ 0       (32768)
//   red [GPB][S][2 halves][2]      @ 32768   (2048)
//   xt  [GPB][D][S] ull            @ 34816   (16384)  x duplicated (x,x)
#define OFF_RED 32768
#define OFF_X   34816
#define SMEM_BYTES (34816 + GPB * D * S * 8)

__device__ float gWV[D * 64 * 4];   // interleaved (w0,w1,v0,v1) per rule pair
__device__ float gCt[D * R];        // c transposed [d][r]
__device__ float gBias[R];

__global__ void anfis_precomp(const float* __restrict__ a,
                              const float* __restrict__ b,
                              const float* __restrict__ c) {
    int r = blockIdx.x, d = threadIdx.x;
    float av = a[r * D + d];
    float bv = fmaxf(b[r * D + d], 1e-8f);
    float w  = 0.70710678118654752f / bv;
    int p = r >> 1, e = r & 1;
    gWV[(d * 64 + p) * 4 + e]     = w;
    gWV[(d * 64 + p) * 4 + 2 + e] = -w * av;
    gCt[d * R + r] = c[r * (D + 1) + d];
    if (d == 0) gBias[r] = c[r * (D + 1) + D];
}

__device__ __forceinline__ ull fma2(ull a, ull b, ull c) {
    ull d;
    asm("fma.rn.f32x2 %0, %1, %2, %3;" : "=l"(d) : "l"(a), "l"(b), "l"(c));
    return d;
}
__device__ __forceinline__ ull add2(ull a, ull b) {
    ull d;
    asm("add.rn.f32x2 %0, %1, %2;" : "=l"(d) : "l"(a), "l"(b));
    return d;
}
#define LDS128I(base, imm, lo, hi) \
    asm volatile("ld.shared.v2.u64 {%0, %1}, [%2 + %3];" \
                 : "=l"(lo), "=l"(hi) : "r"(base), "n"(imm))
#define LDGC(ptr, imm, v) \
    asm volatile("ld.global.nc.u64 %0, [%1 + %2];" \
                 : "=l"(v) : "l"(ptr), "n"(imm))
__device__ __forceinline__ void sts64(uint32_t addr, float lo, float hi) {
    asm volatile("st.shared.v2.f32 [%0], {%1, %2};" :: "r"(addr), "f"(lo), "f"(hi));
}
__device__ __forceinline__ void unpack2(ull v, float& lo, float& hi) {
    asm("mov.b64 {%0, %1}, %2;" : "=f"(lo), "=f"(hi) : "l"(v));
}

// one x-pair (2 samples) of one d: 1 LDS.128 + 6 fma2
#define XSUB(k, p)                                                 \
    {                                                              \
        ull xa, xc, ua, uc;                                        \
        LDS128I(xb, (k) * 128 + (p) * 16, xa, xc);                 \
        ua = fma2(w01, xa, v01);                                   \
        ag[2 * (p)]     = fma2(ua, ua, ag[2 * (p)]);               \
        al[2 * (p)]     = fma2(c01, xa, al[2 * (p)]);              \
        uc = fma2(w01, xc, v01);                                   \
        ag[2 * (p) + 1] = fma2(uc, uc, ag[2 * (p) + 1]);           \
        al[2 * (p) + 1] = fma2(c01, xc, al[2 * (p) + 1]);          \
    }
// one full d-step with compile-time immediates (k = 0..3 inside a chunk)
#define STEP(k)                                                    \
    {                                                              \
        ull w01, v01, c01;                                         \
        LDS128I(wvA, (k) * 1024, w01, v01);                        \
        LDGC(cptr, (k) * 512, c01);                                \
        XSUB(k, 0) XSUB(k, 1) XSUB(k, 2) XSUB(k, 3)                \
        XSUB(k, 4) XSUB(k, 5) XSUB(k, 6) XSUB(k, 7)                \
    }

__global__ void __launch_bounds__(256, 3)
anfis_main(const float* __restrict__ X,
           float* __restrict__ pred,
           float* __restrict__ strengths,
           float* __restrict__ normalized) {
    extern __shared__ float smem[];
    uint32_t sbase;
    {
        uint64_t t;
        asm("cvta.to.shared.u64 %0, %1;" : "=l"(t) : "l"(smem));
        sbase = (uint32_t)t;
    }

    // fill wv table (8192 floats)
    {
        const float4* src = reinterpret_cast<const float4*>(gWV);
        float4* dst = reinterpret_cast<float4*>(smem);
        for (int i = threadIdx.x; i < D * 64; i += blockDim.x)
            dst[i] = src[i];
    }
    // stage X: 64 samples/block; 128 float4s per group; 64 threads per group -> 2 each
    {
        int gg = threadIdx.x >> 6;
        int j0 = threadIdx.x & 63;
        #pragma unroll
        for (int q = 0; q < 2; q++) {
            int idx = j0 + q * 64;          // 0..127
            int row = idx >> 3;             // 0..15
            int seg = idx & 7;              // 0..7
            int n0g = (blockIdx.x * GPB + gg) * S;
            float4 v = *reinterpret_cast<const float4*>(X + (n0g + row) * D + seg * 4);
            uint32_t base = sbase + OFF_X + gg * (D * S * 8) + ((seg * 4) * S + row) * 8;
            sts64(base + 0 * S * 8, v.x, v.x);
            sts64(base + 1 * S * 8, v.y, v.y);
            sts64(base + 2 * S * 8, v.z, v.z);
            sts64(base + 3 * S * 8, v.w, v.w);
        }
    }
    __syncthreads();

    const int lane = threadIdx.x & 31;
    const int warp = threadIdx.x >> 5;
    const int g    = warp >> 1;
    const int half = warp & 1;
    const int rb   = half * 64 + lane * 2;
    const int n0   = (blockIdx.x * GPB + g) * S;

    uint32_t wvA = sbase + (half * 32 + lane) * 16;   // +1024 per d
    uint32_t xb  = sbase + OFF_X + g * (D * S * 8);   // +128 per d
    const float* cptr = gCt + rb;                     // +512B per d

    ull ag[S], al[S];
    #pragma unroll
    for (int s = 0; s < S; s++) { ag[s] = 0ull; al[s] = 0ull; }

    #pragma unroll 1
    for (int dc = 0; dc < 8; dc++) {
        STEP(0) STEP(1) STEP(2) STEP(3)
        wvA  += 4 * 1024;
        xb   += 4 * 128;
        cptr += 4 * 128;        // 4 * 512 bytes
    }

    // ---- epilogue: bias, exp, per-warp reduce, strengths
    ull bb;
    LDGC(gBias + rb, 0, bb);
    const uint32_t redA = sbase + OFF_RED + g * (S * 16);
    #pragma unroll
    for (int s = 0; s < S; s++) {
        float e0, e1, r0, r1;
        unpack2(ag[s], e0, e1);
        unpack2(add2(al[s], bb), r0, r1);
        float s0 = __expf(-e0), s1 = __expf(-e1);
        float ss = s0 + s1;
        float pp = s0 * r0 + s1 * r1;
        #pragma unroll
        for (int off = 16; off > 0; off >>= 1) {
            ss += __shfl_xor_sync(0xffffffffu, ss, off);
            pp += __shfl_xor_sync(0xffffffffu, pp, off);
        }
        if (lane == 0) sts64(redA + s * 16 + half * 8, ss, pp);
        *reinterpret_cast<float2*>(&strengths[(n0 + s) * R + rb]) =
            make_float2(s0, s1);
        ag[s] = 0;
        asm("mov.b64 %0, {%1, %2};" : "=l"(ag[s]) : "f"(s0), "f"(s1));
    }
    __syncthreads();

    // ---- combine halves, write normalized + pred
    #pragma unroll
    for (int s = 0; s < S; s++) {
        float4 rr = *reinterpret_cast<const float4*>(
            &smem[OFF_RED / 4 + g * (S * 4) + s * 4]);   // {ss0,pp0,ss1,pp1}
        float inv = 1.0f / ((rr.x + rr.z) + 1e-8f);
        float s0, s1;
        unpack2(ag[s], s0, s1);
        *reinterpret_cast<float2*>(&normalized[(n0 + s) * R + rb]) =
            make_float2(s0 * inv, s1 * inv);
        if (half == 0 && lane == 0) pred[n0 + s] = (rr.y + rr.w) * inv;
    }
}

extern "C" void kernel_launch(void* const* d_in, const int* in_sizes, int n_in,
                              void* d_out, int out_size) {
    const float* X = (const float*)d_in[0];
    const float* a = (const float*)d_in[1];
    const float* b = (const float*)d_in[2];
    const float* c = (const float*)d_in[3];

    float* out        = (float*)d_out;
    float* pred       = out;
    float* strengths  = out + NS;
    float* normalized = out + NS + NS * R;

    static bool attr_set = false;
    if (!attr_set) {
        cudaFuncSetAttribute(anfis_main,
                             cudaFuncAttributeMaxDynamicSharedMemorySize,
                             SMEM_BYTES);
        attr_set = true;
    }

    anfis_precomp<<<R, D>>>(a, b, c);
    anfis_main<<<NS / (S * GPB), 256, SMEM_BYTES>>>(X, pred, strengths, normalized);
}

// round 8
// speedup vs baseline: 1.6567x; 1.6567x over previous
#include <cuda_runtime.h>
#include <cstdint>

#define NS 65536
#define D  32
#define R  128
#define S  8          // samples per group (group = 2 warps, 64 rules each)
#define GPB 4         // groups per block -> 8 warps, 256 threads

typedef unsigned long long ull;

// smem (bytes): wv [D][64 pairs][w0,w1,v0,v1] @0 (32768)
//               red [GPB][S][2 halves][2]     @32768 (512)
//               xt  [GPB][D][S] ull           @33280 (8192) x duplicated (x,x)
#define OFF_RED 32768
#define OFF_X   33280
#define SMEM_BYTES (33280 + GPB * D * S * 8)

__device__ float gWV[D * 64 * 4];   // interleaved (w0,w1,v0,v1) per rule pair
__device__ float gCt[D * R];        // c transposed [d][r]
__device__ float gBias[R];

__global__ void anfis_precomp(const float* __restrict__ a,
                              const float* __restrict__ b,
                              const float* __restrict__ c) {
    int r = blockIdx.x, d = threadIdx.x;
    float av = a[r * D + d];
    float bv = fmaxf(b[r * D + d], 1e-8f);
    float w  = 0.70710678118654752f / bv;
    int p = r >> 1, e = r & 1;
    gWV[(d * 64 + p) * 4 + e]     = w;
    gWV[(d * 64 + p) * 4 + 2 + e] = -w * av;
    gCt[d * R + r] = c[r * (D + 1) + d];
    if (d == 0) gBias[r] = c[r * (D + 1) + D];
}

__device__ __forceinline__ ull fma2(ull a, ull b, ull c) {
    ull d;
    asm("fma.rn.f32x2 %0, %1, %2, %3;" : "=l"(d) : "l"(a), "l"(b), "l"(c));
    return d;
}
#define LDS128I(base, imm, lo, hi) \
    asm volatile("ld.shared.v2.u64 {%0, %1}, [%2 + %3];" \
                 : "=l"(lo), "=l"(hi) : "r"(base), "n"(imm))
#define LDGC(ptr, imm, v) \
    asm volatile("ld.global.nc.u64 %0, [%1 + %2];" \
                 : "=l"(v) : "l"(ptr), "n"(imm))
__device__ __forceinline__ void sts64(uint32_t addr, float lo, float hi) {
    asm volatile("st.shared.v2.f32 [%0], {%1, %2};" :: "r"(addr), "f"(lo), "f"(hi));
}
__device__ __forceinline__ void unpack2(ull v, float& lo, float& hi) {
    asm("mov.b64 {%0, %1}, %2;" : "=f"(lo), "=f"(hi) : "l"(v));
}
__device__ __forceinline__ ull pack2(float lo, float hi) {
    ull v;
    asm("mov.b64 %0, {%1, %2};" : "=l"(v) : "f"(lo), "f"(hi));
    return v;
}

// prefetch coefficients for step k into (W,V,C)
#define PRE(k, W, V, C)                                            \
    LDS128I(wvA, (k) * 1024, W, V);                                \
    LDGC(cptr, (k) * 512, C);

// compute step k with coefficients (W,V,C); x loads hoisted to the top
#define CMP(k, W, V, C)                                            \
    {                                                              \
        ull x0a, x0c, x1a, x1c, x2a, x2c, x3a, x3c, u;             \
        LDS128I(xb, (k) * 64 + 0,  x0a, x0c);                      \
        LDS128I(xb, (k) * 64 + 16, x1a, x1c);                      \
        LDS128I(xb, (k) * 64 + 32, x2a, x2c);                      \
        LDS128I(xb, (k) * 64 + 48, x3a, x3c);                      \
        u = fma2(W, x0a, V); ag0 = fma2(u, u, ag0); al0 = fma2(C, x0a, al0); \
        u = fma2(W, x0c, V); ag1 = fma2(u, u, ag1); al1 = fma2(C, x0c, al1); \
        u = fma2(W, x1a, V); ag2 = fma2(u, u, ag2); al2 = fma2(C, x1a, al2); \
        u = fma2(W, x1c, V); ag3 = fma2(u, u, ag3); al3 = fma2(C, x1c, al3); \
        u = fma2(W, x2a, V); ag4 = fma2(u, u, ag4); al4 = fma2(C, x2a, al4); \
        u = fma2(W, x2c, V); ag5 = fma2(u, u, ag5); al5 = fma2(C, x2c, al5); \
        u = fma2(W, x3a, V); ag6 = fma2(u, u, ag6); al6 = fma2(C, x3a, al6); \
        u = fma2(W, x3c, V); ag7 = fma2(u, u, ag7); al7 = fma2(C, x3c, al7); \
    }

#define EPI(s, AG, AL)                                             \
    {                                                              \
        float e0, e1, r0, r1;                                      \
        unpack2(AG, e0, e1);                                       \
        unpack2(AL, r0, r1);                                       \
        float s0 = __expf(-e0), s1 = __expf(-e1);                  \
        AG = pack2(s0, s1);                                        \
        float ss = s0 + s1, pp = s0 * r0 + s1 * r1;                \
        _Pragma("unroll")                                          \
        for (int off = 16; off > 0; off >>= 1) {                   \
            ss += __shfl_xor_sync(0xffffffffu, ss, off);           \
            pp += __shfl_xor_sync(0xffffffffu, pp, off);           \
        }                                                          \
        if (lane == 0) sts64(redA + (s) * 16 + half * 8, ss, pp);  \
        *reinterpret_cast<float2*>(&strengths[(n0 + (s)) * R + rb]) = \
            make_float2(s0, s1);                                   \
    }

#define FIN(s, AG)                                                 \
    {                                                              \
        float4 rr = *reinterpret_cast<const float4*>(              \
            &smem[OFF_RED / 4 + g * 32 + (s) * 4]);                \
        float inv = 1.0f / ((rr.x + rr.z) + 1e-8f);                \
        float s0, s1;                                              \
        unpack2(AG, s0, s1);                                       \
        *reinterpret_cast<float2*>(&normalized[(n0 + (s)) * R + rb]) = \
            make_float2(s0 * inv, s1 * inv);                       \
        if (half == 0 && lane == 0) pred[n0 + (s)] = (rr.y + rr.w) * inv; \
    }

__global__ void __launch_bounds__(256, 3)
anfis_main(const float* __restrict__ X,
           float* __restrict__ pred,
           float* __restrict__ strengths,
           float* __restrict__ normalized) {
    extern __shared__ float smem[];
    uint32_t sbase;
    {
        uint64_t t;
        asm("cvta.to.shared.u64 %0, %1;" : "=l"(t) : "l"(smem));
        sbase = (uint32_t)t;
    }

    // fill wv table (8192 floats)
    {
        const float4* src = reinterpret_cast<const float4*>(gWV);
        float4* dst = reinterpret_cast<float4*>(smem);
        for (int i = threadIdx.x; i < D * 64; i += blockDim.x)
            dst[i] = src[i];
    }
    // stage X: thread t handles float4 j=t&63 of group g=t>>6
    {
        int gg  = threadIdx.x >> 6;
        int j   = threadIdx.x & 63;
        int row = j >> 3;
        int seg = j & 7;
        int n0g = (blockIdx.x * GPB + gg) * S;
        float4 v = *reinterpret_cast<const float4*>(X + (n0g + row) * D + seg * 4);
        uint32_t base = sbase + OFF_X + gg * (D * S * 8) + ((seg * 4) * S + row) * 8;
        sts64(base + 0 * S * 8, v.x, v.x);
        sts64(base + 1 * S * 8, v.y, v.y);
        sts64(base + 2 * S * 8, v.z, v.z);
        sts64(base + 3 * S * 8, v.w, v.w);
    }
    __syncthreads();

    const int lane = threadIdx.x & 31;
    const int warp = threadIdx.x >> 5;
    const int g    = warp >> 1;
    const int half = warp & 1;
    const int rb   = half * 64 + lane * 2;
    const int n0   = (blockIdx.x * GPB + g) * S;

    const uint32_t wvA  = sbase + (half * 32 + lane) * 16;
    const uint32_t xb   = sbase + OFF_X + g * (D * S * 8);
    const uint32_t redA = sbase + OFF_RED + g * 128;
    const float* cptr = gCt + rb;

    ull bb;
    LDGC(gBias + rb, 0, bb);
    ull ag0 = 0, ag1 = 0, ag2 = 0, ag3 = 0, ag4 = 0, ag5 = 0, ag6 = 0, ag7 = 0;
    ull al0 = bb, al1 = bb, al2 = bb, al3 = bb, al4 = bb, al5 = bb, al6 = bb, al7 = bb;

    ull wA, vA, cA, wB, vB, cB;
    PRE(0, wA, vA, cA)
    PRE(1,  wB, vB, cB)  CMP(0,  wA, vA, cA)
    PRE(2,  wA, vA, cA)  CMP(1,  wB, vB, cB)
    PRE(3,  wB, vB, cB)  CMP(2,  wA, vA, cA)
    PRE(4,  wA, vA, cA)  CMP(3,  wB, vB, cB)
    PRE(5,  wB, vB, cB)  CMP(4,  wA, vA, cA)
    PRE(6,  wA, vA, cA)  CMP(5,  wB, vB, cB)
    PRE(7,  wB, vB, cB)  CMP(6,  wA, vA, cA)
    PRE(8,  wA, vA, cA)  CMP(7,  wB, vB, cB)
    PRE(9,  wB, vB, cB)  CMP(8,  wA, vA, cA)
    PRE(10, wA, vA, cA)  CMP(9,  wB, vB, cB)
    PRE(11, wB, vB, cB)  CMP(10, wA, vA, cA)
    PRE(12, wA, vA, cA)  CMP(11, wB, vB, cB)
    PRE(13, wB, vB, cB)  CMP(12, wA, vA, cA)
    PRE(14, wA, vA, cA)  CMP(13, wB, vB, cB)
    PRE(15, wB, vB, cB)  CMP(14, wA, vA, cA)
    PRE(16, wA, vA, cA)  CMP(15, wB, vB, cB)
    PRE(17, wB, vB, cB)  CMP(16, wA, vA, cA)
    PRE(18, wA, vA, cA)  CMP(17, wB, vB, cB)
    PRE(19, wB, vB, cB)  CMP(18, wA, vA, cA)
    PRE(20, wA, vA, cA)  CMP(19, wB, vB, cB)
    PRE(21, wB, vB, cB)  CMP(20, wA, vA, cA)
    PRE(22, wA, vA, cA)  CMP(21, wB, vB, cB)
    PRE(23, wB, vB, cB)  CMP(22, wA, vA, cA)
    PRE(24, wA, vA, cA)  CMP(23, wB, vB, cB)
    PRE(25, wB, vB, cB)  CMP(24, wA, vA, cA)
    PRE(26, wA, vA, cA)  CMP(25, wB, vB, cB)
    PRE(27, wB, vB, cB)  CMP(26, wA, vA, cA)
    PRE(28, wA, vA, cA)  CMP(27, wB, vB, cB)
    PRE(29, wB, vB, cB)  CMP(28, wA, vA, cA)
    PRE(30, wA, vA, cA)  CMP(29, wB, vB, cB)
    PRE(31, wB, vB, cB)  CMP(30, wA, vA, cA)
    CMP(31, wB, vB, cB)

    EPI(0, ag0, al0) EPI(1, ag1, al1) EPI(2, ag2, al2) EPI(3, ag3, al3)
    EPI(4, ag4, al4) EPI(5, ag5, al5) EPI(6, ag6, al6) EPI(7, ag7, al7)
    __syncthreads();
    FIN(0, ag0) FIN(1, ag1) FIN(2, ag2) FIN(3, ag3)
    FIN(4, ag4) FIN(5, ag5) FIN(6, ag6) FIN(7, ag7)
}

extern "C" void kernel_launch(void* const* d_in, const int* in_sizes, int n_in,
                              void* d_out, int out_size) {
    const float* X = (const float*)d_in[0];
    const float* a = (const float*)d_in[1];
    const float* b = (const float*)d_in[2];
    const float* c = (const float*)d_in[3];

    float* out        = (float*)d_out;
    float* pred       = out;
    float* strengths  = out + NS;
    float* normalized = out + NS + NS * R;

    static bool attr_set = false;
    if (!attr_set) {
        cudaFuncSetAttribute(anfis_main,
                             cudaFuncAttributeMaxDynamicSharedMemorySize,
                             SMEM_BYTES);
        attr_set = true;
    }

    anfis_precomp<<<R, D>>>(a, b, c);
    anfis_main<<<NS / (S * GPB), 256, SMEM_BYTES>>>(X, pred, strengths, normalized);
}